// round 2
// baseline (speedup 1.0000x reference)
#include <cuda_runtime.h>
#include <cuda_bf16.h>
#include <cstdint>

#define NROWS 8192
#define DIM   512
#define BM    128
#define BN    128
#define BK    64
#define STAGES 3
#define KCHUNKS (DIM / BK)        // 8

// Scratch (allocation-free rule: __device__ globals)
__device__ __nv_bfloat16 g_sb[(size_t)NROWS * DIM];
__device__ __nv_bfloat16 g_tb[(size_t)NROWS * DIM];
__device__ float g_ssq[NROWS];
__device__ float g_tsq[NROWS];

__device__ __forceinline__ uint32_t smem_u32(const void* p) {
    return (uint32_t)__cvta_generic_to_shared(p);
}
#define SW128(o) ((o) ^ ((((uint32_t)(o)) >> 3) & 0x70u))

__device__ __forceinline__ void cp_async16(uint32_t smem_addr, const void* gptr) {
    asm volatile("cp.async.cg.shared.global [%0], [%1], 16;" :: "r"(smem_addr), "l"(gptr));
}
__device__ __forceinline__ void cp_commit() {
    asm volatile("cp.async.commit_group;" ::: "memory");
}
template <int N>
__device__ __forceinline__ void cp_wait() {
    asm volatile("cp.async.wait_group %0;" :: "n"(N) : "memory");
}

__device__ __forceinline__ void ldmatrix_x4(uint32_t& r0, uint32_t& r1, uint32_t& r2, uint32_t& r3,
                                            uint32_t addr) {
    asm volatile("ldmatrix.sync.aligned.m8n8.x4.shared.b16 {%0,%1,%2,%3}, [%4];"
                 : "=r"(r0), "=r"(r1), "=r"(r2), "=r"(r3) : "r"(addr));
}

__device__ __forceinline__ void mma_16816(float* c, const uint32_t* a, uint32_t b0, uint32_t b1) {
    asm volatile(
        "mma.sync.aligned.m16n8k16.row.col.f32.bf16.bf16.f32 "
        "{%0,%1,%2,%3}, {%4,%5,%6,%7}, {%8,%9}, {%0,%1,%2,%3};"
        : "+f"(c[0]), "+f"(c[1]), "+f"(c[2]), "+f"(c[3])
        : "r"(a[0]), "r"(a[1]), "r"(a[2]), "r"(a[3]), "r"(b0), "r"(b1));
}

// ---------------------------------------------------------------------------
// Kernel 1: fp32 -> bf16 conversion + row square-norms (fp32-exact)
// ---------------------------------------------------------------------------
__global__ __launch_bounds__(128) void convert_kernel(const float* __restrict__ s,
                                                      const float* __restrict__ t) {
    int row = blockIdx.x;
    const float* src;
    __nv_bfloat16* dst;
    float* sqout;
    if (row < NROWS) {
        src = s + (size_t)row * DIM;
        dst = g_sb + (size_t)row * DIM;
        sqout = g_ssq + row;
    } else {
        int r = row - NROWS;
        src = t + (size_t)r * DIM;
        dst = g_tb + (size_t)r * DIM;
        sqout = g_tsq + r;
    }
    int tid = threadIdx.x;  // 0..127, DIM/4 = 128 float4 per row
    float4 v = reinterpret_cast<const float4*>(src)[tid];
    float acc = v.x * v.x + v.y * v.y + v.z * v.z + v.w * v.w;

    __nv_bfloat162 lo = __floats2bfloat162_rn(v.x, v.y);
    __nv_bfloat162 hi = __floats2bfloat162_rn(v.z, v.w);
    reinterpret_cast<__nv_bfloat162*>(dst)[2 * tid]     = lo;
    reinterpret_cast<__nv_bfloat162*>(dst)[2 * tid + 1] = hi;

    #pragma unroll
    for (int o = 16; o > 0; o >>= 1) acc += __shfl_xor_sync(0xFFFFFFFFu, acc, o);
    __shared__ float partial[4];
    if ((tid & 31) == 0) partial[tid >> 5] = acc;
    __syncthreads();
    if (tid == 0) *sqout = partial[0] + partial[1] + partial[2] + partial[3];
}

// ---------------------------------------------------------------------------
// Kernel 2: bf16 HMMA GEMM (mma.sync.m16n8k16) + fused distance epilogue
// ---------------------------------------------------------------------------
#define STAGE_BYTES (2 * BM * 128)        // A(16KB) + B(16KB)

extern __shared__ __align__(1024) char dyn_smem[];

__global__ __launch_bounds__(256, 2) void dist_kernel(float* __restrict__ out) {
    const int tid  = threadIdx.x;
    const int wid  = tid >> 5;
    const int lane = tid & 31;
    const int warp_m = wid >> 2;       // 0..1
    const int warp_n = wid & 3;        // 0..3
    const int m0 = blockIdx.y * BM;
    const int n0 = blockIdx.x * BN;

    const int cm = tid >> 3;           // base row for cp.async (i adds 32 rows)
    const int ck8 = tid & 7;           // 16B column within the 128B row
    const __nv_bfloat16* ga = g_sb + (size_t)(m0 + cm) * DIM + ck8 * 8;
    const __nv_bfloat16* gb = g_tb + (size_t)(n0 + cm) * DIM + ck8 * 8;
    const uint32_t smem_base = smem_u32(dyn_smem);

    float acc[4][4][4];
    #pragma unroll
    for (int mi = 0; mi < 4; mi++)
        #pragma unroll
        for (int ni = 0; ni < 4; ni++)
            #pragma unroll
            for (int k = 0; k < 4; k++) acc[mi][ni][k] = 0.0f;

    const uint32_t a_row = (uint32_t)(warp_m * 64 + (lane & 15));
    const uint32_t a_colh = (uint32_t)((lane >> 4) * 16);
    const uint32_t b_row = (uint32_t)(warp_n * 32 + (lane & 7) + ((lane & 16) ? 8 : 0));
    const uint32_t b_colh = (uint32_t)(((lane >> 3) & 1) * 16);

    // Prologue: stages 0..2 load K-chunks 0..2
    #pragma unroll
    for (int st = 0; st < STAGES; st++) {
        const uint32_t abase = smem_base + st * STAGE_BYTES;
        const uint32_t bbase = abase + BM * 128;
        #pragma unroll
        for (int i = 0; i < 4; i++) {
            const uint32_t so = SW128(((uint32_t)(cm + i * 32)) * 128u + (uint32_t)ck8 * 16u);
            cp_async16(abase + so, ga + (size_t)(i * 32) * DIM + st * BK);
            cp_async16(bbase + so, gb + (size_t)(i * 32) * DIM + st * BK);
        }
        cp_commit();
    }

    for (int kc = 0; kc < KCHUNKS; kc++) {
        cp_wait<STAGES - 1>();
        __syncthreads();

        const int st = kc % STAGES;
        const uint32_t abase = smem_base + st * STAGE_BYTES;
        const uint32_t bbase = abase + BM * 128;

        #pragma unroll
        for (int ks = 0; ks < 4; ks++) {
            uint32_t af[4][4];
            uint32_t bf[2][4];
            #pragma unroll
            for (int mi = 0; mi < 4; mi++) {
                const uint32_t off = (a_row + mi * 16) * 128u + (uint32_t)(ks * 32) + a_colh;
                ldmatrix_x4(af[mi][0], af[mi][1], af[mi][2], af[mi][3], abase + SW128(off));
            }
            #pragma unroll
            for (int g = 0; g < 2; g++) {
                const uint32_t off = (b_row + g * 16) * 128u + (uint32_t)(ks * 32) + b_colh;
                ldmatrix_x4(bf[g][0], bf[g][1], bf[g][2], bf[g][3], bbase + SW128(off));
            }
            #pragma unroll
            for (int mi = 0; mi < 4; mi++) {
                #pragma unroll
                for (int ni = 0; ni < 4; ni++) {
                    const int g = ni >> 1, p = ni & 1;
                    mma_16816(acc[mi][ni], af[mi], bf[g][p * 2], bf[g][p * 2 + 1]);
                }
            }
        }
        __syncthreads();

        const int knext = kc + STAGES;
        if (knext < KCHUNKS) {
            #pragma unroll
            for (int i = 0; i < 4; i++) {
                const uint32_t so = SW128(((uint32_t)(cm + i * 32)) * 128u + (uint32_t)ck8 * 16u);
                cp_async16(abase + so, ga + (size_t)(i * 32) * DIM + knext * BK);
                cp_async16(bbase + so, gb + (size_t)(i * 32) * DIM + knext * BK);
            }
        }
        cp_commit();  // empty groups in the tail keep wait_group<2> exact
    }

    // ---------------- Epilogue: dist = ssq + tsq - 2*cross ----------------
    const int groupID = lane >> 2;
    const int tig = lane & 3;
    #pragma unroll
    for (int mi = 0; mi < 4; mi++) {
        const int row0 = m0 + warp_m * 64 + mi * 16 + groupID;
        const int row1 = row0 + 8;
        const float sq0 = g_ssq[row0];
        const float sq1 = g_ssq[row1];
        float* o0 = out + (size_t)row0 * NROWS;
        float* o1 = out + (size_t)row1 * NROWS;
        #pragma unroll
        for (int ni = 0; ni < 4; ni++) {
            const int col = n0 + warp_n * 32 + ni * 8 + tig * 2;
            const float tq0 = g_tsq[col];
            const float tq1 = g_tsq[col + 1];
            float2 v0, v1;
            v0.x = sq0 + tq0 - 2.0f * acc[mi][ni][0];
            v0.y = sq0 + tq1 - 2.0f * acc[mi][ni][1];
            v1.x = sq1 + tq0 - 2.0f * acc[mi][ni][2];
            v1.y = sq1 + tq1 - 2.0f * acc[mi][ni][3];
            *reinterpret_cast<float2*>(o0 + col) = v0;
            *reinterpret_cast<float2*>(o1 + col) = v1;
        }
    }
}

// ---------------------------------------------------------------------------
extern "C" void kernel_launch(void* const* d_in, const int* in_sizes, int n_in,
                              void* d_out, int out_size) {
    const float* s = (const float*)d_in[0];
    const float* t = (const float*)d_in[1];
    float* out = (float*)d_out;

    cudaFuncSetAttribute(dist_kernel, cudaFuncAttributeMaxDynamicSharedMemorySize,
                         STAGES * STAGE_BYTES);

    convert_kernel<<<2 * NROWS, 128>>>(s, t);
    dim3 grid(NROWS / BN, NROWS / BM);
    dist_kernel<<<grid, 256, STAGES * STAGE_BYTES>>>(out);
}